// round 1
// baseline (speedup 1.0000x reference)
#include <cuda_runtime.h>
#include <cuda_bf16.h>

// MultiGaussianReadoutLayer: fused per-instance linear (mu), per-instance
// linear (sigma, F_OUT^2 outputs), and M-sample affine eps application.
// Shapes: B=32, H=24, N=500 -> O=12000 instances, F_IN=64, F_OUT=4, M=16.
//
// Strategy: CTA = 8 instances x 32 batch rows (256 threads, thread=(b,o)).
// Weights for the 8 instances cached in smem (one coalesced load, reused 32x).
// sigma (16 floats) + mu (4 floats) accumulate in registers, reused across
// the M=16 eps samples. eps/out accesses are float4, fully coalesced.

#define B_    32
#define O_    12000
#define FIN   64
#define FOUT  4
#define M_    16
#define OB    8     // instances per CTA

// per-instance smem strides, padded +4 floats so the 8 distinct o-addresses
// of a warp's LDS.128 land on bank offsets {0,4,...,28}: conflict-free.
#define SW_STRIDE (FIN*FOUT*FOUT + 4)   // 1028
#define MW_STRIDE (FIN*FOUT + 4)        // 260

__global__ void __launch_bounds__(256, 2)
mgr_kernel(const float* __restrict__ x,
           const float* __restrict__ mu_w,
           const float* __restrict__ mu_b,
           const float* __restrict__ sigma_w,
           const float* __restrict__ sigma_b,
           const float* __restrict__ eps,
           float* __restrict__ out)
{
    __shared__ __align__(16) float sw[OB * SW_STRIDE];  // sigma_w block
    __shared__ __align__(16) float mw[OB * MW_STRIDE];  // mu_w block
    __shared__ float sb[OB * 16];
    __shared__ float mb[OB * 4];

    const int tid    = threadIdx.x;
    const int o_base = blockIdx.x * OB;

    // ---- stage weights: fully coalesced float4 global reads ----
    {
        const float4* src_s = (const float4*)(sigma_w + (size_t)o_base * 1024);
        #pragma unroll
        for (int i = tid; i < OB * 1024 / 4; i += 256) {
            int o = i >> 8;          // 256 float4 per instance
            int r = i & 255;
            *(float4*)(sw + o * SW_STRIDE + r * 4) = src_s[i];
        }
        const float4* src_m = (const float4*)(mu_w + (size_t)o_base * 256);
        #pragma unroll
        for (int i = tid; i < OB * 256 / 4; i += 256) {
            int o = i >> 6;          // 64 float4 per instance
            int r = i & 63;
            *(float4*)(mw + o * MW_STRIDE + r * 4) = src_m[i];
        }
        if (tid < OB * 16) sb[tid] = sigma_b[(size_t)o_base * 16 + tid];
        if (tid < OB * 4)  mb[tid] = mu_b[(size_t)o_base * 4 + tid];
    }
    __syncthreads();

    const int o_l = tid & (OB - 1);   // instance within block
    const int b   = tid >> 3;         // batch row 0..31
    const int og  = o_base + o_l;

    const float* swp = sw + o_l * SW_STRIDE;
    const float* mwp = mw + o_l * MW_STRIDE;

    float sig[16];
    float mu[4];
    #pragma unroll
    for (int k = 0; k < 16; k++) sig[k] = sb[o_l * 16 + k];
    #pragma unroll
    for (int l = 0; l < 4;  l++) mu[l]  = mb[o_l * 4 + l];

    // ---- mainloop: two matvecs over F_IN=64 ----
    // x row is 256B/thread; each thread covers its row fully -> every fetched
    // sector is consumed (L1 absorbs the per-instruction scatter).
    const float4* xg = (const float4*)(x + ((size_t)b * O_ + og) * FIN);
    #pragma unroll
    for (int f4 = 0; f4 < FIN / 4; f4++) {
        float4 xv = __ldg(&xg[f4]);
        #pragma unroll
        for (int j = 0; j < 4; j++) {
            const int f = f4 * 4 + j;
            const float xf = (j == 0) ? xv.x : (j == 1) ? xv.y : (j == 2) ? xv.z : xv.w;

            float4 m4 = *(const float4*)(mwp + f * 4);
            mu[0] += xf * m4.x; mu[1] += xf * m4.y;
            mu[2] += xf * m4.z; mu[3] += xf * m4.w;

            #pragma unroll
            for (int k4 = 0; k4 < 4; k4++) {
                float4 s4 = *(const float4*)(swp + f * 16 + k4 * 4);
                sig[k4 * 4 + 0] += xf * s4.x;
                sig[k4 * 4 + 1] += xf * s4.y;
                sig[k4 * 4 + 2] += xf * s4.z;
                sig[k4 * 4 + 3] += xf * s4.w;
            }
        }
    }

    // ---- eps application: out[m,l] = mu[l] + sum_f sig[l*4+f] * eps[m,f] ----
    // eps/out layout [M, B, O, 4]: per-warp float4 = 4x128B coalesced segments.
    const size_t beo = (size_t)b * O_ + og;
    #pragma unroll
    for (int m = 0; m < M_; m++) {
        const size_t idx = ((size_t)m * B_ * O_ + beo) * 4;
        float4 e = __ldg((const float4*)(eps + idx));
        float4 r;
        r.x = mu[0] + sig[0]  * e.x + sig[1]  * e.y + sig[2]  * e.z + sig[3]  * e.w;
        r.y = mu[1] + sig[4]  * e.x + sig[5]  * e.y + sig[6]  * e.z + sig[7]  * e.w;
        r.z = mu[2] + sig[8]  * e.x + sig[9]  * e.y + sig[10] * e.z + sig[11] * e.w;
        r.w = mu[3] + sig[12] * e.x + sig[13] * e.y + sig[14] * e.z + sig[15] * e.w;
        *(float4*)(out + idx) = r;
    }
}

extern "C" void kernel_launch(void* const* d_in, const int* in_sizes, int n_in,
                              void* d_out, int out_size)
{
    const float* x       = (const float*)d_in[0];
    const float* mu_w    = (const float*)d_in[1];
    const float* mu_b    = (const float*)d_in[2];
    const float* sigma_w = (const float*)d_in[3];
    const float* sigma_b = (const float*)d_in[4];
    const float* eps     = (const float*)d_in[5];
    float* out           = (float*)d_out;

    dim3 grid(O_ / OB);   // 1500 CTAs
    dim3 block(256);
    mgr_kernel<<<grid, block>>>(x, mu_w, mu_b, sigma_w, sigma_b, eps, out);
}